// round 12
// baseline (speedup 1.0000x reference)
#include <cuda_runtime.h>
#include <math.h>

#define DIM    512
#define HID    256
#define POOL   20
#define NB     1024
#define NL     64
#define TOPK   5
#define NCHUNK 32          // P computed in 32 chunks of 16 d
#define CHD    16
#define GRID_A (NCHUNK + POOL + 1)

// ---------------- device scratch (no allocations allowed) ----------------
__device__ float g_scale, g_vw, g_bn2;
__device__ int   g_flag;
__device__ int   g_ctr = 0;
__device__ float g_kinv[POOL], g_bk[POOL];
__device__ float g_pPk[NCHUNK * POOL];   // partial P.k per chunk
__device__ float g_pPn2[NCHUNK];         // partial ||P||^2 per chunk
__device__ float g_pPb[NCHUNK];          // partial P.b2 per chunk
__device__ float4 g_recW[NB];            // by b:   {w0,w1,w2,w3}
__device__ int4   g_recM[NB];            // by b:   {bits(w4), packed ids, len, b}
__device__ float4 g_recWp[NB];           // permuted (sorted by quality)
__device__ int4   g_recMp[NB];

// ---------------- reduction helpers ----------------
__device__ __forceinline__ float warpSum(float v) {
    #pragma unroll
    for (int o = 16; o; o >>= 1) v += __shfl_xor_sync(0xffffffffu, v, o);
    return v;
}
__device__ float blockSum(float v, float* s_red) {
    int lane = threadIdx.x & 31, wid = threadIdx.x >> 5;
    int nw = blockDim.x >> 5;
    v = warpSum(v);
    if (lane == 0) s_red[wid] = v;
    __syncthreads();
    if (wid == 0) {
        float x = (lane < nw) ? s_red[lane] : 0.0f;
        x = warpSum(x);
        if (lane == 0) s_red[0] = x;
    }
    __syncthreads();
    float r = s_red[0];
    __syncthreads();
    return r;
}

// softmax(scale*sims) -> top5 (strict >, lowest idx on ties = JAX) -> record
__device__ __forceinline__ void finish_record(int b, float qb, const float* sims,
                                              float scale) {
    float z[POOL];
    #pragma unroll
    for (int p = 0; p < POOL; p++) z[p] = sims[p] * scale;
    float m = -1e30f;
    #pragma unroll
    for (int p = 0; p < POOL; p++) m = fmaxf(m, z[p]);
    float sum = 0.0f;
    #pragma unroll
    for (int p = 0; p < POOL; p++) { z[p] = expf(z[p] - m); sum += z[p]; }
    float inv = 1.0f / sum;
    #pragma unroll
    for (int p = 0; p < POOL; p++) z[p] *= inv;

    float w[TOPK]; int pi[TOPK];
    float pv = 1e30f; int pidx = -1;
    #pragma unroll
    for (int k = 0; k < TOPK; k++) {
        float bv = -1e30f; int bi = 0;
        #pragma unroll
        for (int p = 0; p < POOL; p++) {
            float v = z[p];
            bool elig = (v < pv) || (v == pv && p > pidx);
            if (elig && v > bv) { bv = v; bi = p; }
        }
        w[k] = bv; pi[k] = bi;
        pv = bv; pidx = bi;
    }
    float lf = 5.0f + 59.0f * (1.0f - qb / 5.0f);
    int li = (int)truncf(lf);
    li = min(max(li, 5), 64);
    int packed = pi[0] | (pi[1] << 6) | (pi[2] << 12) | (pi[3] << 18) | (pi[4] << 24);
    g_recW[b] = make_float4(w[0], w[1], w[2], w[3]);
    g_recM[b] = make_int4(__float_as_int(w[4]), packed, li, b);
}

// ---------------- K_AB: fused precompute + selection + sort ----------------
// blocks 0..31 : P chunk (16 d each) partials   (block 0 also g_vw)
// blocks 32..51: key p -> kinv, b2.k
// block  52    : scale, flag, bn2
// LAST arriving block: reduce partials, all 1024 records, sort by quality,
//                      emit permuted record arrays.
__global__ void __launch_bounds__(256) kAB(
        const float* __restrict__ q,  const float* __restrict__ keys,
        const float* __restrict__ w1, const float* __restrict__ b1,
        const float* __restrict__ lng,const float* __restrict__ lnb,
        const float* __restrict__ w2, const float* __restrict__ b2) {
    __shared__ float s_red[32];
    int bx = blockIdx.x, t = threadIdx.x;     // blockDim = 256

    if (bx < NCHUNK) {
        __shared__ float s_hr[HID];
        __shared__ float s_part[HID];
        __shared__ float s_Pv[CHD];
        float wv = w1[t];
        float mw = blockSum(wv, s_red) * (1.0f / (float)HID);
        float cv = wv - mw;
        float var = blockSum(cv * cv, s_red) * (1.0f / (float)HID);
        if (bx == 0 && t == 0) g_vw = var;
        s_hr[t] = fmaxf(cv, 0.0f);
        __syncthreads();

        int d0 = bx * CHD;
        int dd = t & (CHD - 1), jg = t / CHD;       // 16 j-groups of 16
        float acc = 0.0f;
        #pragma unroll
        for (int jj = 0; jj < HID / CHD; jj++) {
            int j = jg * (HID / CHD) + jj;
            acc = fmaf(s_hr[j], w2[j * DIM + d0 + dd], acc);
        }
        s_part[t] = acc;
        __syncthreads();

        if (t < 32) {
            float Pv = 0.0f;
            if (t < CHD) {
                #pragma unroll
                for (int g = 0; g < HID / CHD; g++) Pv += s_part[g * CHD + t];
                s_Pv[t] = Pv;
            }
            __syncwarp();
            float pvv = (t < CHD) ? s_Pv[t] : 0.0f;
            float pn2 = warpSum(pvv * pvv);
            float pb  = warpSum((t < CHD) ? pvv * b2[d0 + t] : 0.0f);
            if (t == 0) { g_pPn2[bx] = pn2; g_pPb[bx] = pb; }
        }
        __syncthreads();
        int w = t >> 5, lane = t & 31;
        #pragma unroll
        for (int rep = 0; rep < 3; rep++) {
            int p = w + rep * 8;
            if (p < POOL) {
                float v = (lane < CHD) ? s_Pv[lane] * keys[p * DIM + d0 + lane] : 0.0f;
                v = warpSum(v);
                if (lane == 0) g_pPk[bx * POOL + p] = v;
            }
        }
    } else if (bx < NCHUNK + POOL) {
        int p = bx - NCHUNK;
        float k2 = 0.0f, bk = 0.0f;
        #pragma unroll
        for (int r = 0; r < DIM / 256; r++) {
            int d = t + r * 256;
            float kv = keys[p * DIM + d];
            k2 = fmaf(kv, kv, k2);
            bk = fmaf(b2[d], kv, bk);
        }
        k2 = blockSum(k2, s_red);
        bk = blockSum(bk, s_red);
        if (t == 0) { g_kinv[p] = 1.0f / fmaxf(sqrtf(k2), 1e-8f); g_bk[p] = bk; }
    } else {
        float qs = 0.0f; int ok = 1;
        #pragma unroll
        for (int i = t; i < NB; i += 256) { float qv = q[i]; qs += qv; ok &= (qv >= 0.0f); }
        qs = blockSum(qs, s_red);
        if (t == 0) g_scale = 1.0f + 0.5f * (qs / (float)NB);
        ok = ok && (b1[t] == 0.0f) && (lnb[t] == 0.0f) && (lng[t] == 1.0f);
        int all = __syncthreads_and(ok);
        if (t == 0) g_flag = all;
        float bv = 0.0f;
        #pragma unroll
        for (int r = 0; r < DIM / 256; r++) { float x = b2[t + r * 256]; bv = fmaf(x, x, bv); }
        bv = blockSum(bv, s_red);
        if (t == 0) g_bn2 = bv;
    }

    // ---- arrival: last block runs the epilogue ----
    __shared__ int s_last;
    __syncthreads();
    if (t == 0) {
        __threadfence();
        int ticket = atomicAdd(&g_ctr, 1);
        s_last = (ticket == GRID_A - 1) ? 1 : 0;
        if (s_last) __threadfence();
    }
    __syncthreads();
    if (!s_last) return;

    // ======== epilogue (single block, 256 threads) ========
    __shared__ float e_Pk[POOL];
    __shared__ float e_sc[2];                 // pn2, pb
    __shared__ float e_key[NB];
    __shared__ int   e_val[NB];

    if (t < POOL) {
        float acc = 0.0f;
        #pragma unroll
        for (int c = 0; c < NCHUNK; c++) acc += g_pPk[c * POOL + t];
        e_Pk[t] = acc;
    } else if (t == POOL) {
        float acc = 0.0f;
        #pragma unroll
        for (int c = 0; c < NCHUNK; c++) acc += g_pPn2[c];
        e_sc[0] = acc;
    } else if (t == POOL + 1) {
        float acc = 0.0f;
        #pragma unroll
        for (int c = 0; c < NCHUNK; c++) acc += g_pPb[c];
        e_sc[1] = acc;
    }
    __syncthreads();

    if (g_flag) {
        float scale = g_scale, vw = g_vw, bn2 = g_bn2;
        float pn2 = e_sc[0], pb = e_sc[1];
        #pragma unroll
        for (int r = 0; r < NB / 256; r++) {
            int b = t + r * 256;
            float qb = q[b];
            float a = qb * rsqrtf(qb * qb * vw + 1e-5f);
            float n2 = fmaxf(a * a * pn2 + 2.0f * a * pb + bn2, 0.0f);
            float qinv = 1.0f / fmaxf(sqrtf(n2), 1e-8f);
            float sims[POOL];
            #pragma unroll
            for (int p = 0; p < POOL; p++)
                sims[p] = (a * e_Pk[p] + g_bk[p]) * g_kinv[p] * qinv;
            finish_record(b, qb, sims, scale);
        }
    } else {
        // general fallback (cold, correct): serial over b, block-parallel GEMV
        __shared__ float s_hr2[HID];
        __shared__ float s_query[DIM];
        __shared__ float s_sims[POOL];
        __shared__ float s_qinv;
        for (int b = 0; b < NB; b++) {
            float qb = q[b];
            float h = fmaf(qb, w1[t], b1[t]);
            float mu = blockSum(h, s_red) * (1.0f / (float)HID);
            float c = h - mu;
            float var = blockSum(c * c, s_red) * (1.0f / (float)HID);
            float hn = c * rsqrtf(var + 1e-5f) * lng[t] + lnb[t];
            s_hr2[t] = fmaxf(hn, 0.0f);
            __syncthreads();
            float n2p = 0.0f;
            #pragma unroll
            for (int r = 0; r < 2; r++) {
                int d = t + r * HID;
                float acc = b2[d];
                for (int j = 0; j < HID; j++) acc = fmaf(s_hr2[j], w2[j * DIM + d], acc);
                s_query[d] = acc;
                n2p += acc * acc;
            }
            float n2 = blockSum(n2p, s_red);
            if (t == 0) s_qinv = 1.0f / fmaxf(sqrtf(fmaxf(n2, 0.0f)), 1e-8f);
            __syncthreads();
            if (t < POOL) {
                float acc = 0.0f;
                for (int d = 0; d < DIM; d++) acc = fmaf(s_query[d], keys[t * DIM + d], acc);
                s_sims[t] = acc * g_kinv[t] * s_qinv;
            }
            __syncthreads();
            if (t == 0) {
                float sims[POOL];
                #pragma unroll
                for (int p = 0; p < POOL; p++) sims[p] = s_sims[p];
                finish_record(b, qb, sims, g_scale);
            }
            __syncthreads();
        }
    }
    __syncthreads();

    // ---- bitonic sort b's by (quality asc, b asc) -> grouping for K2 hoist ----
    #pragma unroll
    for (int r = 0; r < NB / 256; r++) {
        int i = t + r * 256;
        e_key[i] = q[i];
        e_val[i] = i;
    }
    __syncthreads();
    for (int k = 2; k <= NB; k <<= 1) {
        for (int j = k >> 1; j > 0; j >>= 1) {
            #pragma unroll
            for (int r = 0; r < NB / 256; r++) {
                int i = t + r * 256;
                int ixj = i ^ j;
                if (ixj > i) {
                    bool up = ((i & k) == 0);
                    float ka = e_key[i], kb = e_key[ixj];
                    int va = e_val[i], vb = e_val[ixj];
                    bool gt = (ka > kb) || (ka == kb && va > vb);
                    if (up ? gt : !gt) {
                        e_key[i] = kb; e_key[ixj] = ka;
                        e_val[i] = vb; e_val[ixj] = va;
                    }
                }
            }
            __syncthreads();
        }
    }
    // permuted record arrays (g_recW/M visible: written pre-__syncthreads in-block)
    #pragma unroll
    for (int r = 0; r < NB / 256; r++) {
        int i = t + r * 256;
        int b = e_val[i];
        g_recWp[i] = g_recW[b];
        g_recMp[i] = g_recM[b];
    }
    if (t == 0) g_ctr = 0;    // reset for next graph replay
}

// ---------------- K2: main output kernel ----------------
// grid: (16 sorted-slot tiles of 64, 64 l), 128 threads; thread owns one float4 of D
__global__ void __launch_bounds__(128) k2_output(const float* __restrict__ pe,
                                                 float* __restrict__ out) {
    __shared__ float4 s_pe[POOL * 128];     // 40 KB: PE[:, l, :] for this l
    __shared__ float4 s_recW[64];
    __shared__ int4   s_recM[64];

    int t  = threadIdx.x;
    int l  = blockIdx.y;
    int b0 = blockIdx.x * 64;

    const float4* peg = (const float4*)pe;
    #pragma unroll
    for (int p = 0; p < POOL; p++)
        s_pe[p * 128 + t] = __ldg(&peg[(p * NL + l) * 128 + t]);

    if (t < 64) {
        s_recW[t] = g_recWp[b0 + t];
        s_recM[t] = g_recMp[b0 + t];
    }
    __syncthreads();

    float4* outv = (float4*)out;
    int po_prev = -1;
    float4 a0 = make_float4(0,0,0,0), a1 = a0, a2 = a0, a3 = a0, a4 = a0;

    for (int bi = 0; bi < 64; bi++) {
        float4 wv = s_recW[bi];               // LDS.128 broadcast
        int4   mv = s_recM[bi];               // LDS.128 broadcast
        float4 r = make_float4(0.0f, 0.0f, 0.0f, 0.0f);
        if (l < mv.z) {
            int po = mv.y;
            if (po != po_prev) {              // warp-uniform; sorted -> rare
                a0 = s_pe[(( po        & 63) << 7) + t];
                a1 = s_pe[(((po >> 6 ) & 63) << 7) + t];
                a2 = s_pe[(((po >> 12) & 63) << 7) + t];
                a3 = s_pe[(((po >> 18) & 63) << 7) + t];
                a4 = s_pe[(((po >> 24) & 63) << 7) + t];
                po_prev = po;
            }
            float c4 = __int_as_float(mv.x);
            r.x = fmaf(c4, a4.x, fmaf(wv.w, a3.x, fmaf(wv.z, a2.x, fmaf(wv.y, a1.x, wv.x * a0.x))));
            r.y = fmaf(c4, a4.y, fmaf(wv.w, a3.y, fmaf(wv.z, a2.y, fmaf(wv.y, a1.y, wv.x * a0.y))));
            r.z = fmaf(c4, a4.z, fmaf(wv.w, a3.z, fmaf(wv.z, a2.z, fmaf(wv.y, a1.z, wv.x * a0.z))));
            r.w = fmaf(c4, a4.w, fmaf(wv.w, a3.w, fmaf(wv.z, a2.w, fmaf(wv.y, a1.w, wv.x * a0.w))));
        }
        size_t ob = (((size_t)mv.w * NL) + (size_t)l) * 128 + (size_t)t;
        __stcs(&outv[ob], r);                 // streaming: keep PE hot in L2
    }
}

// ---------------- launch ----------------
extern "C" void kernel_launch(void* const* d_in, const int* in_sizes, int n_in,
                              void* d_out, int out_size) {
    (void)in_sizes; (void)n_in; (void)out_size;
    // 0: x_embed (unused)  1: quality_score  2: prompt_keys  3: prompt_embeddings
    // 4: w1  5: b1  6: ln_g  7: ln_b  8: w2  9: b2
    const float* q    = (const float*)d_in[1];
    const float* keys = (const float*)d_in[2];
    const float* pe   = (const float*)d_in[3];
    const float* w1   = (const float*)d_in[4];
    const float* b1   = (const float*)d_in[5];
    const float* lng  = (const float*)d_in[6];
    const float* lnb  = (const float*)d_in[7];
    const float* w2   = (const float*)d_in[8];
    const float* b2   = (const float*)d_in[9];
    float* out = (float*)d_out;

    kAB<<<GRID_A, 256>>>(q, keys, w1, b1, lng, lnb, w2, b2);
    k2_output<<<dim3(16, 64), 128>>>(pe, out);
}

// round 14
// speedup vs baseline: 2.0261x; 2.0261x over previous
#include <cuda_runtime.h>
#include <math.h>

#define DIM    512
#define HID    256
#define POOL   20
#define NB     1024
#define NL     64
#define TOPK   5
#define NCHUNK 32          // P computed in 32 chunks of 16 d
#define CHD    16

// ---------------- device scratch (no allocations allowed) ----------------
__device__ float g_scale, g_vw, g_bn2;
__device__ int   g_flag;
__device__ float g_kinv[POOL], g_bk[POOL];
__device__ float g_pPk[NCHUNK * POOL];   // partial P.k per chunk
__device__ float g_pPn2[NCHUNK];         // partial ||P||^2 per chunk
__device__ float g_pPb[NCHUNK];          // partial P.b2 per chunk
__device__ float4 g_recW[NB];            // {w0,w1,w2,w3}
__device__ int4   g_recM[NB];            // {bits(w4), packed 5x6-bit ids, len, 0}

// ---------------- reduction helpers ----------------
__device__ __forceinline__ float warpSum(float v) {
    #pragma unroll
    for (int o = 16; o; o >>= 1) v += __shfl_xor_sync(0xffffffffu, v, o);
    return v;
}
__device__ float blockSum(float v, float* s_red) {
    int lane = threadIdx.x & 31, wid = threadIdx.x >> 5;
    int nw = blockDim.x >> 5;
    v = warpSum(v);
    if (lane == 0) s_red[wid] = v;
    __syncthreads();
    if (wid == 0) {
        float x = (lane < nw) ? s_red[lane] : 0.0f;
        x = warpSum(x);
        if (lane == 0) s_red[0] = x;
    }
    __syncthreads();
    float r = s_red[0];
    __syncthreads();
    return r;
}

// ---------------- K_A: fused precompute, 53 independent blocks ----------------
// blocks 0..31 : P chunk (16 d each) + partial Pk/Pn2/Pb  (block 0 also g_vw)
// blocks 32..51: key p = bx-32 -> kinv, b2.k
// block  52    : scale, flag, bn2
__global__ void __launch_bounds__(256) kA_precompute(
        const float* __restrict__ q,  const float* __restrict__ keys,
        const float* __restrict__ w1, const float* __restrict__ b1,
        const float* __restrict__ lng,const float* __restrict__ lnb,
        const float* __restrict__ w2, const float* __restrict__ b2) {
    __shared__ float s_red[32];
    int bx = blockIdx.x, t = threadIdx.x;     // blockDim = 256

    if (bx < NCHUNK) {
        __shared__ float s_hr[HID];
        __shared__ float s_part[HID];
        __shared__ float s_Pv[CHD];
        // local w1 stats (recomputed identically per block -> deterministic)
        float wv = w1[t];
        float mw = blockSum(wv, s_red) * (1.0f / (float)HID);
        float cv = wv - mw;
        float var = blockSum(cv * cv, s_red) * (1.0f / (float)HID);
        if (bx == 0 && t == 0) g_vw = var;
        s_hr[t] = fmaxf(cv, 0.0f);
        __syncthreads();

        // P[d0+dd] = sum_j s_hr[j]*w2[j,d0+dd]; thread = (jg of 16, dd of 16)
        int d0 = bx * CHD;
        int dd = t & (CHD - 1), jg = t / CHD;       // 16 j-groups of 16
        float acc = 0.0f;
        #pragma unroll
        for (int jj = 0; jj < HID / CHD; jj++) {
            int j = jg * (HID / CHD) + jj;
            acc = fmaf(s_hr[j], w2[j * DIM + d0 + dd], acc);
        }
        s_part[t] = acc;
        __syncthreads();

        if (t < 32) {
            float Pv = 0.0f;
            if (t < CHD) {
                #pragma unroll
                for (int g = 0; g < HID / CHD; g++) Pv += s_part[g * CHD + t];
                s_Pv[t] = Pv;
            }
            __syncwarp();
            float pvv = (t < CHD) ? s_Pv[t] : 0.0f;
            float pn2 = warpSum(pvv * pvv);
            float pb  = warpSum((t < CHD) ? pvv * b2[d0 + t] : 0.0f);
            if (t == 0) { g_pPn2[bx] = pn2; g_pPb[bx] = pb; }
        }
        __syncthreads();
        // P.k partials spread across 8 warps (<=3 pools each)
        int w = t >> 5, lane = t & 31;
        #pragma unroll
        for (int rep = 0; rep < 3; rep++) {
            int p = w + rep * 8;
            if (p < POOL) {
                float v = (lane < CHD) ? s_Pv[lane] * keys[p * DIM + d0 + lane] : 0.0f;
                v = warpSum(v);
                if (lane == 0) g_pPk[bx * POOL + p] = v;
            }
        }
    } else if (bx < NCHUNK + POOL) {
        int p = bx - NCHUNK;
        float k2 = 0.0f, bk = 0.0f;
        #pragma unroll
        for (int r = 0; r < DIM / 256; r++) {
            int d = t + r * 256;
            float kv = keys[p * DIM + d];
            k2 = fmaf(kv, kv, k2);
            bk = fmaf(b2[d], kv, bk);
        }
        k2 = blockSum(k2, s_red);
        bk = blockSum(bk, s_red);
        if (t == 0) { g_kinv[p] = 1.0f / fmaxf(sqrtf(k2), 1e-8f); g_bk[p] = bk; }
    } else {
        // scale = 1 + 0.5*mean(q); flag; bn2
        float qs = 0.0f; int ok = 1;
        #pragma unroll
        for (int i = t; i < NB; i += 256) { float qv = q[i]; qs += qv; ok &= (qv >= 0.0f); }
        qs = blockSum(qs, s_red);
        if (t == 0) g_scale = 1.0f + 0.5f * (qs / (float)NB);
        ok = ok && (b1[t] == 0.0f) && (lnb[t] == 0.0f) && (lng[t] == 1.0f);
        int all = __syncthreads_and(ok);
        if (t == 0) g_flag = all;
        float bv = 0.0f;
        #pragma unroll
        for (int r = 0; r < DIM / 256; r++) { float x = b2[t + r * 256]; bv = fmaf(x, x, bv); }
        bv = blockSum(bv, s_red);
        if (t == 0) g_bn2 = bv;
    }
}

// softmax(scale*sims) -> top5 (strict >, lowest idx on ties = JAX) -> record
__device__ __forceinline__ void finish_record(int b, float qb, const float* sims,
                                              float scale) {
    float z[POOL];
    #pragma unroll
    for (int p = 0; p < POOL; p++) z[p] = sims[p] * scale;
    float m = -1e30f;
    #pragma unroll
    for (int p = 0; p < POOL; p++) m = fmaxf(m, z[p]);
    float sum = 0.0f;
    #pragma unroll
    for (int p = 0; p < POOL; p++) { z[p] = expf(z[p] - m); sum += z[p]; }
    float inv = 1.0f / sum;
    #pragma unroll
    for (int p = 0; p < POOL; p++) z[p] *= inv;

    float w[TOPK]; int pi[TOPK];
    float pv = 1e30f; int pidx = -1;
    #pragma unroll
    for (int k = 0; k < TOPK; k++) {
        float bv = -1e30f; int bi = 0;
        #pragma unroll
        for (int p = 0; p < POOL; p++) {
            float v = z[p];
            bool elig = (v < pv) || (v == pv && p > pidx);
            if (elig && v > bv) { bv = v; bi = p; }
        }
        w[k] = bv; pi[k] = bi;
        pv = bv; pidx = bi;
    }
    float lf = 5.0f + 59.0f * (1.0f - qb / 5.0f);
    int li = (int)truncf(lf);
    li = min(max(li, 5), 64);
    int packed = pi[0] | (pi[1] << 6) | (pi[2] << 12) | (pi[3] << 18) | (pi[4] << 24);
    g_recW[b] = make_float4(w[0], w[1], w[2], w[3]);
    g_recM[b] = make_int4(__float_as_int(w[4]), packed, li, 0);
}

// ---------------- K1: thread-per-b selection (grid 8 x 128) ----------------
__global__ void __launch_bounds__(128) k1_select(
        const float* __restrict__ q,  const float* __restrict__ keys,
        const float* __restrict__ w1, const float* __restrict__ b1,
        const float* __restrict__ lng,const float* __restrict__ lnb,
        const float* __restrict__ w2, const float* __restrict__ b2) {
    int bx = blockIdx.x, t = threadIdx.x;   // blockDim = 128
    __shared__ float s_red[32];
    __shared__ float s_Pk[POOL], s_kinv[POOL], s_bk[POOL];
    __shared__ float s_pn2, s_pb;

    if (g_flag) {
        if (t < POOL) {
            float acc = 0.0f;
            #pragma unroll
            for (int c = 0; c < NCHUNK; c++) acc += g_pPk[c * POOL + t];
            s_Pk[t] = acc;
            s_kinv[t] = g_kinv[t];
            s_bk[t] = g_bk[t];
        } else if (t == POOL) {
            float acc = 0.0f;
            #pragma unroll
            for (int c = 0; c < NCHUNK; c++) acc += g_pPn2[c];
            s_pn2 = acc;
        } else if (t == POOL + 1) {
            float acc = 0.0f;
            #pragma unroll
            for (int c = 0; c < NCHUNK; c++) acc += g_pPb[c];
            s_pb = acc;
        }
        __syncthreads();

        int b = bx * 128 + t;
        float qb = q[b];
        float a = qb * rsqrtf(qb * qb * g_vw + 1e-5f);
        float n2 = fmaxf(a * a * s_pn2 + 2.0f * a * s_pb + g_bn2, 0.0f);
        float qinv = 1.0f / fmaxf(sqrtf(n2), 1e-8f);
        float sims[POOL];
        #pragma unroll
        for (int p = 0; p < POOL; p++)
            sims[p] = (a * s_Pk[p] + s_bk[p]) * s_kinv[p] * qinv;
        finish_record(b, qb, sims, g_scale);
    } else {
        // general fallback (cold, correct): block-serial over 128 b's
        __shared__ float s_hr[HID];
        __shared__ float s_query[DIM];
        __shared__ float s_sims[POOL];
        __shared__ float s_qinv;
        for (int bb = 0; bb < 128; bb++) {
            int b = bx * 128 + bb;
            float qb = q[b];
            float h0 = fmaf(qb, w1[t], b1[t]);
            float h1 = fmaf(qb, w1[t + 128], b1[t + 128]);
            float mu = blockSum(h0 + h1, s_red) * (1.0f / (float)HID);
            float c0 = h0 - mu, c1 = h1 - mu;
            float var = blockSum(c0 * c0 + c1 * c1, s_red) * (1.0f / (float)HID);
            float rs = rsqrtf(var + 1e-5f);
            s_hr[t]       = fmaxf(c0 * rs * lng[t]       + lnb[t], 0.0f);
            s_hr[t + 128] = fmaxf(c1 * rs * lng[t + 128] + lnb[t + 128], 0.0f);
            __syncthreads();
            float n2p = 0.0f;
            #pragma unroll
            for (int r = 0; r < 4; r++) {
                int d = t + r * 128;
                float acc = b2[d];
                for (int j = 0; j < HID; j++) acc = fmaf(s_hr[j], w2[j * DIM + d], acc);
                s_query[d] = acc;
                n2p += acc * acc;
            }
            float n2 = blockSum(n2p, s_red);
            if (t == 0) s_qinv = 1.0f / fmaxf(sqrtf(fmaxf(n2, 0.0f)), 1e-8f);
            __syncthreads();
            if (t < POOL) {
                float acc = 0.0f;
                for (int d = 0; d < DIM; d++) acc = fmaf(s_query[d], keys[t * DIM + d], acc);
                s_sims[t] = acc * g_kinv[t] * s_qinv;
            }
            __syncthreads();
            if (t == 0) {
                float sims[POOL];
                #pragma unroll
                for (int p = 0; p < POOL; p++) sims[p] = s_sims[p];
                finish_record(b, qb, sims, g_scale);
            }
            __syncthreads();
        }
    }
}

// ---------------- K2: main output kernel ----------------
// grid (16 b-tiles of 64, 64 l), 256 threads: thread = (half, col).
// col owns one float4 of D; half 0 -> bi 0..31, half 1 -> bi 32..63.
// Same 40KB smem as the 128-thread version but 2x warps -> 62% occupancy.
__global__ void __launch_bounds__(256) k2_output(const float* __restrict__ pe,
                                                 float* __restrict__ out) {
    __shared__ float4 s_pe[POOL * 128];     // 40 KB: PE[:, l, :] for this l
    __shared__ float4 s_recW[64];
    __shared__ int4   s_recM[64];

    int t    = threadIdx.x;
    int col  = t & 127;
    int half = t >> 7;
    int l    = blockIdx.y;
    int b0   = blockIdx.x * 64;

    const float4* peg = (const float4*)pe;
    #pragma unroll
    for (int p = half; p < POOL; p += 2)
        s_pe[p * 128 + col] = __ldg(&peg[(p * NL + l) * 128 + col]);

    if (t < 64) {
        s_recW[t] = g_recW[b0 + t];
        s_recM[t] = g_recM[b0 + t];
    }
    __syncthreads();

    float4* outv = (float4*)out;
    size_t ob = (((size_t)(b0 + half * 32) * NL) + (size_t)l) * 128 + (size_t)col;

    #pragma unroll 4
    for (int k = 0; k < 32; k++) {
        int bi = half * 32 + k;
        float4 wv = s_recW[bi];               // LDS.128 broadcast
        int4   mv = s_recM[bi];               // LDS.128 broadcast
        float4 r = make_float4(0.0f, 0.0f, 0.0f, 0.0f);
        if (l < mv.z) {
            int po = mv.y;
            float c4 = __int_as_float(mv.x);
            float4 a0 = s_pe[(( po        & 63) << 7) + col];
            float4 a1 = s_pe[(((po >> 6 ) & 63) << 7) + col];
            float4 a2 = s_pe[(((po >> 12) & 63) << 7) + col];
            float4 a3 = s_pe[(((po >> 18) & 63) << 7) + col];
            float4 a4 = s_pe[(((po >> 24) & 63) << 7) + col];
            r.x = fmaf(c4, a4.x, fmaf(wv.w, a3.x, fmaf(wv.z, a2.x, fmaf(wv.y, a1.x, wv.x * a0.x))));
            r.y = fmaf(c4, a4.y, fmaf(wv.w, a3.y, fmaf(wv.z, a2.y, fmaf(wv.y, a1.y, wv.x * a0.y))));
            r.z = fmaf(c4, a4.z, fmaf(wv.w, a3.z, fmaf(wv.z, a2.z, fmaf(wv.y, a1.z, wv.x * a0.z))));
            r.w = fmaf(c4, a4.w, fmaf(wv.w, a3.w, fmaf(wv.z, a2.w, fmaf(wv.y, a1.w, wv.x * a0.w))));
        }
        __stcs(&outv[ob + (size_t)k * (NL * 128)], r);   // streaming: keep PE hot in L2
    }
}

// ---------------- launch ----------------
extern "C" void kernel_launch(void* const* d_in, const int* in_sizes, int n_in,
                              void* d_out, int out_size) {
    (void)in_sizes; (void)n_in; (void)out_size;
    // 0: x_embed (unused)  1: quality_score  2: prompt_keys  3: prompt_embeddings
    // 4: w1  5: b1  6: ln_g  7: ln_b  8: w2  9: b2
    const float* q    = (const float*)d_in[1];
    const float* keys = (const float*)d_in[2];
    const float* pe   = (const float*)d_in[3];
    const float* w1   = (const float*)d_in[4];
    const float* b1   = (const float*)d_in[5];
    const float* lng  = (const float*)d_in[6];
    const float* lnb  = (const float*)d_in[7];
    const float* w2   = (const float*)d_in[8];
    const float* b2   = (const float*)d_in[9];
    float* out = (float*)d_out;

    kA_precompute<<<NCHUNK + POOL + 1, 256>>>(q, keys, w1, b1, lng, lnb, w2, b2);
    k1_select<<<8, 128>>>(q, keys, w1, b1, lng, lnb, w2, b2);
    k2_output<<<dim3(16, 64), 256>>>(pe, out);
}